// round 6
// baseline (speedup 1.0000x reference)
#include <cuda_runtime.h>

#define EMB 64
#define NSEG_MAX 4097
#define THREADS 256
#define POOL_GRID (148 * 8)      // persistent: one full wave at 8 CTAs/SM

__device__ float g_wvo[EMB];     // w_value @ w_out
__device__ float g_c;            // b_value.w_out + b_out
__device__ float g_b0;           // b_out[0]
__device__ int   g_starts[NSEG_MAX];
__device__ int   g_counter;      // work-stealing cursor

// Kernel 1: segment-bounds scan over sorted ids + fused-head precompute
// + work counter reset. Block 0 threads 0..63 do the tiny GEMM in parallel
// with the 4MB ids stream.
__global__ __launch_bounds__(THREADS)
void bounds_kernel(const int*   __restrict__ ids,
                   const float* __restrict__ w_value,
                   const float* __restrict__ b_value,
                   const float* __restrict__ w_out,
                   const float* __restrict__ b_out,
                   int Btot, int Nimg) {
    const int tid = threadIdx.x;
    const int i   = blockIdx.x * THREADS + tid;

    if (blockIdx.x == 0) {
        if (tid < EMB) {
            float s = 0.f;
#pragma unroll
            for (int h = 0; h < EMB; ++h)
                s = fmaf(__ldg(w_value + tid * EMB + h), __ldg(w_out + h), s);
            g_wvo[tid] = s;
            if (tid == 0) {
                float c = 0.f;
                for (int h = 0; h < EMB; ++h) c = fmaf(__ldg(b_value + h), __ldg(w_out + h), c);
                g_c  = c + __ldg(b_out);
                g_b0 = __ldg(b_out);
            }
        }
        if (tid == 64) g_counter = 0;   // reset stealing cursor every launch
    }

    if (i < Btot) {
        const int cur = __ldg(ids + i);
        if (i == 0) {
            for (int j = 0; j <= cur; ++j) g_starts[j] = 0;
        } else {
            const int prev = __ldg(ids + i - 1);
            for (int j = prev + 1; j <= cur; ++j) g_starts[j] = i;
        }
        if (i == Btot - 1) {
            for (int j = cur + 1; j <= Nimg; ++j) g_starts[j] = Btot;
        }
    }
}

// Kernel 2: persistent CTAs, dynamic segment stealing. Per segment:
// 16 threads/row float4 loads; only the SCORE partial is shfl-reduced per
// row; exp replicated per 16-lane group; VALUE partials reduced once per CTA.
__global__ __launch_bounds__(THREADS, 8)
void pool_kernel(const float* __restrict__ emb,
                 const float* __restrict__ w_attn,
                 float* __restrict__ out,
                 int Btot, int Nimg) {
    const int tid = threadIdx.x;
    const int grp = tid & 15;          // column slice [4*grp, 4*grp+4)
    const int rl  = tid >> 4;          // row slot 0..15
    const int wid = tid >> 5;

    const float4 wa = reinterpret_cast<const float4*>(w_attn)[grp];
    const float4 wv = reinterpret_cast<const float4*>(g_wvo)[grp];

    __shared__ float s_se[8], s_sev[8];
    __shared__ float s_r;
    __shared__ int   s_n;

    for (;;) {
        if (tid == 0) s_n = atomicAdd(&g_counter, 1);
        __syncthreads();
        const int n = s_n;
        __syncthreads();               // s_n safe before next iteration's overwrite
        if (n >= Nimg) return;

        const int start = g_starts[n];
        const int end   = g_starts[n + 1];
        const int cnt   = end - start;

        float se0 = 0.f, sev0 = 0.f, se1 = 0.f, sev1 = 0.f;
        float se2 = 0.f, sev2 = 0.f, se3 = 0.f, sev3 = 0.f;

        const int mid = start + (cnt & ~63);

        // ---- main loop: unpredicated 64-row blocks ----
        for (int base = start; base < mid; base += 64) {
            float4 e[4];
#pragma unroll
            for (int u = 0; u < 4; ++u)
                e[u] = reinterpret_cast<const float4*>(emb + (size_t)(base + u * 16 + rl) * EMB)[grp];
#pragma unroll
            for (int u = 0; u < 4; ++u) {
                float sp = e[u].x * wa.x + e[u].y * wa.y + e[u].z * wa.z + e[u].w * wa.w;
                float vp = e[u].x * wv.x + e[u].y * wv.y + e[u].z * wv.z + e[u].w * wv.w;
#pragma unroll
                for (int o = 8; o; o >>= 1) sp += __shfl_xor_sync(0xffffffffu, sp, o);
                const float ex = __expf(sp);           // replicated on 16 lanes
                if      (u == 0) { se0 += ex; sev0 = fmaf(ex, vp, sev0); }
                else if (u == 1) { se1 += ex; sev1 = fmaf(ex, vp, sev1); }
                else if (u == 2) { se2 += ex; sev2 = fmaf(ex, vp, sev2); }
                else             { se3 += ex; sev3 = fmaf(ex, vp, sev3); }
            }
        }

        // ---- masked tail block ----
        if (mid < end) {
            float4 e[4];
            bool   v[4];
#pragma unroll
            for (int u = 0; u < 4; ++u) {
                const int row = mid + u * 16 + rl;
                v[u] = row < end;
                e[u] = make_float4(0.f, 0.f, 0.f, 0.f);
                if (v[u]) e[u] = reinterpret_cast<const float4*>(emb + (size_t)row * EMB)[grp];
            }
#pragma unroll
            for (int u = 0; u < 4; ++u) {
                float sp = e[u].x * wa.x + e[u].y * wa.y + e[u].z * wa.z + e[u].w * wa.w;
                float vp = e[u].x * wv.x + e[u].y * wv.y + e[u].z * wv.z + e[u].w * wv.w;
#pragma unroll
                for (int o = 8; o; o >>= 1) sp += __shfl_xor_sync(0xffffffffu, sp, o);
                float ex = v[u] ? __expf(sp) : 0.f;
                if      (u == 0) { se0 += ex; sev0 = fmaf(ex, vp, sev0); }
                else if (u == 1) { se1 += ex; sev1 = fmaf(ex, vp, sev1); }
                else if (u == 2) { se2 += ex; sev2 = fmaf(ex, vp, sev2); }
                else             { se3 += ex; sev3 = fmaf(ex, vp, sev3); }
            }
        }

        float se  = (se0 + se1) + (se2 + se3);
        float sev = (sev0 + sev1) + (sev2 + sev3);
        se += __shfl_xor_sync(0xffffffffu, se, 16);
#pragma unroll
        for (int o = 16; o; o >>= 1) sev += __shfl_xor_sync(0xffffffffu, sev, o);

        if ((tid & 31) == 0) { s_se[wid] = se; s_sev[wid] = sev; }
        __syncthreads();

        if (tid == 0) {
            float SE = 0.f, SEV = 0.f;
#pragma unroll
            for (int w = 0; w < 8; ++w) { SE += s_se[w]; SEV += s_sev[w]; }
            const float r = (cnt == 0) ? g_b0 : (SEV / SE + g_c);
            out[Btot + n]        = r;          // r_images
            out[Btot + Nimg + n] = (float)n;   // unique_ids
            s_r = r;
        }
        __syncthreads();

        const float r = s_r;
        for (int i = start + tid; i < end; i += THREADS) out[i] = r;  // r_reflections
    }
}

extern "C" void kernel_launch(void* const* d_in, const int* in_sizes, int n_in,
                              void* d_out, int out_size) {
    const float* emb     = (const float*)d_in[0];
    const int*   ids     = (const int*)  d_in[1];
    const float* w_attn  = (const float*)d_in[2];
    // d_in[3] = b_attn: cancels under softmax shift invariance
    const float* w_value = (const float*)d_in[4];
    const float* b_value = (const float*)d_in[5];
    const float* w_out   = (const float*)d_in[6];
    const float* b_out   = (const float*)d_in[7];
    float* out = (float*)d_out;

    const int Btot = in_sizes[0] / EMB;          // 1048576
    const int Nimg = (out_size - Btot) / 2;      // 4096

    bounds_kernel<<<(Btot + THREADS - 1) / THREADS, THREADS>>>(
        ids, w_value, b_value, w_out, b_out, Btot, Nimg);
    pool_kernel<<<POOL_GRID, THREADS>>>(emb, w_attn, out, Btot, Nimg);
}

// round 7
// speedup vs baseline: 1.1727x; 1.1727x over previous
#include <cuda_runtime.h>

#define EMB 64
#define NSEG_MAX 4097
#define THREADS 256
#define WARPS_PER_CTA 8

__device__ float g_wvo[EMB];     // w_value @ w_out
__device__ float g_c;            // b_value.w_out + b_out
__device__ float g_b0;           // b_out[0]
__device__ int   g_starts[NSEG_MAX];

// Kernel 1: segment-bounds scan over sorted ids + fused-head precompute.
__global__ __launch_bounds__(THREADS)
void bounds_kernel(const int*   __restrict__ ids,
                   const float* __restrict__ w_value,
                   const float* __restrict__ b_value,
                   const float* __restrict__ w_out,
                   const float* __restrict__ b_out,
                   int Btot, int Nimg) {
    const int tid = threadIdx.x;
    const int i   = blockIdx.x * THREADS + tid;

    if (blockIdx.x == 0 && tid < EMB) {
        float s = 0.f;
#pragma unroll
        for (int h = 0; h < EMB; ++h)
            s = fmaf(__ldg(w_value + tid * EMB + h), __ldg(w_out + h), s);
        g_wvo[tid] = s;
        if (tid == 0) {
            float c = 0.f;
            for (int h = 0; h < EMB; ++h) c = fmaf(__ldg(b_value + h), __ldg(w_out + h), c);
            g_c  = c + __ldg(b_out);
            g_b0 = __ldg(b_out);
        }
    }

    if (i < Btot) {
        const int cur = __ldg(ids + i);
        if (i == 0) {
            for (int j = 0; j <= cur; ++j) g_starts[j] = 0;
        } else {
            const int prev = __ldg(ids + i - 1);
            for (int j = prev + 1; j <= cur; ++j) g_starts[j] = i;
        }
        if (i == Btot - 1) {
            for (int j = cur + 1; j <= Nimg; ++j) g_starts[j] = Btot;
        }
    }
}

// Kernel 2: ONE WARP PER SEGMENT. No shared memory, no __syncthreads — each
// warp streams its segment independently (8-way unrolled float4 loads,
// 16 lanes/row). Score partial reduced with 4 shfls/row; exp replicated;
// value partials reduced once per segment.
__global__ __launch_bounds__(THREADS, 4)
void pool_kernel(const float* __restrict__ emb,
                 const float* __restrict__ w_attn,
                 float* __restrict__ out,
                 int Btot, int Nimg) {
    const int n = blockIdx.x * WARPS_PER_CTA + (threadIdx.x >> 5);  // segment id
    if (n >= Nimg) return;

    const int lane = threadIdx.x & 31;
    const int grp  = lane & 15;        // column slice [4*grp, 4*grp+4)
    const int half = lane >> 4;        // row slot 0/1 within the warp

    const float4 wa = reinterpret_cast<const float4*>(w_attn)[grp];
    const float4 wv = reinterpret_cast<const float4*>(g_wvo)[grp];

    const int start = g_starts[n];
    const int end   = g_starts[n + 1];
    const int cnt   = end - start;

    float se0 = 0.f, sev0 = 0.f, se1 = 0.f, sev1 = 0.f;
    float se2 = 0.f, sev2 = 0.f, se3 = 0.f, sev3 = 0.f;

    const int mid = start + (cnt & ~15);   // 16 rows per iteration

    // ---- main loop: 8 independent LDG.128 (512B each) issued back-to-back ----
    for (int base = start; base < mid; base += 16) {
        float4 e[8];
#pragma unroll
        for (int u = 0; u < 8; ++u)
            e[u] = reinterpret_cast<const float4*>(emb + (size_t)(base + u * 2 + half) * EMB)[grp];
#pragma unroll
        for (int u = 0; u < 8; ++u) {
            float sp = e[u].x * wa.x + e[u].y * wa.y + e[u].z * wa.z + e[u].w * wa.w;
            float vp = e[u].x * wv.x + e[u].y * wv.y + e[u].z * wv.z + e[u].w * wv.w;
#pragma unroll
            for (int o = 8; o; o >>= 1) sp += __shfl_xor_sync(0xffffffffu, sp, o);
            const float ex = __expf(sp);             // replicated on the 16-lane group
            if      ((u & 3) == 0) { se0 += ex; sev0 = fmaf(ex, vp, sev0); }
            else if ((u & 3) == 1) { se1 += ex; sev1 = fmaf(ex, vp, sev1); }
            else if ((u & 3) == 2) { se2 += ex; sev2 = fmaf(ex, vp, sev2); }
            else                   { se3 += ex; sev3 = fmaf(ex, vp, sev3); }
        }
    }

    // ---- masked tail (up to 15 rows) ----
    if (mid < end) {
#pragma unroll
        for (int u = 0; u < 8; ++u) {
            const int row = mid + u * 2 + half;
            const bool v = row < end;
            float4 e = make_float4(0.f, 0.f, 0.f, 0.f);
            if (v) e = reinterpret_cast<const float4*>(emb + (size_t)row * EMB)[grp];
            float sp = e.x * wa.x + e.y * wa.y + e.z * wa.z + e.w * wa.w;
            float vp = e.x * wv.x + e.y * wv.y + e.z * wv.z + e.w * wv.w;
#pragma unroll
            for (int o = 8; o; o >>= 1) sp += __shfl_xor_sync(0xffffffffu, sp, o);
            const float ex = v ? __expf(sp) : 0.f;
            se0 += ex; sev0 = fmaf(ex, vp, sev0);
        }
    }

    // ---- once-per-segment reduction (intra-warp only) ----
    float se  = (se0 + se1) + (se2 + se3);
    float sev = (sev0 + sev1) + (sev2 + sev3);
    se += __shfl_xor_sync(0xffffffffu, se, 16);      // se replicated in 16-groups
#pragma unroll
    for (int o = 16; o; o >>= 1) sev += __shfl_xor_sync(0xffffffffu, sev, o);

    const float r = (cnt == 0) ? g_b0 : (sev / se + g_c);  // replicated on all lanes

    if (lane == 0) {
        out[Btot + n]        = r;          // r_images
        out[Btot + Nimg + n] = (float)n;   // unique_ids
    }
    for (int i = start + lane; i < end; i += 32) out[i] = r;   // r_reflections
}

extern "C" void kernel_launch(void* const* d_in, const int* in_sizes, int n_in,
                              void* d_out, int out_size) {
    const float* emb     = (const float*)d_in[0];
    const int*   ids     = (const int*)  d_in[1];
    const float* w_attn  = (const float*)d_in[2];
    // d_in[3] = b_attn: cancels under softmax shift invariance
    const float* w_value = (const float*)d_in[4];
    const float* b_value = (const float*)d_in[5];
    const float* w_out   = (const float*)d_in[6];
    const float* b_out   = (const float*)d_in[7];
    float* out = (float*)d_out;

    const int Btot = in_sizes[0] / EMB;          // 1048576
    const int Nimg = (out_size - Btot) / 2;      // 4096

    bounds_kernel<<<(Btot + THREADS - 1) / THREADS, THREADS>>>(
        ids, w_value, b_value, w_out, b_out, Btot, Nimg);
    const int nwarp_ctas = (Nimg + WARPS_PER_CTA - 1) / WARPS_PER_CTA;  // 512
    pool_kernel<<<nwarp_ctas, THREADS>>>(emb, w_attn, out, Btot, Nimg);
}

// round 8
// speedup vs baseline: 1.2150x; 1.0361x over previous
#include <cuda_runtime.h>

#define EMB 64
#define NSEG_MAX 4097
#define THREADS 256

__device__ float g_wvo[EMB];     // w_value @ w_out
__device__ float g_c;            // b_value.w_out + b_out
__device__ float g_b0;           // b_out[0]
__device__ int   g_starts[NSEG_MAX];

// Kernel 1: segment-bounds scan over sorted ids + fused-head precompute.
__global__ __launch_bounds__(THREADS)
void bounds_kernel(const int*   __restrict__ ids,
                   const float* __restrict__ w_value,
                   const float* __restrict__ b_value,
                   const float* __restrict__ w_out,
                   const float* __restrict__ b_out,
                   int Btot, int Nimg) {
    const int tid = threadIdx.x;
    const int i   = blockIdx.x * THREADS + tid;

    if (blockIdx.x == 0 && tid < EMB) {
        float s = 0.f;
#pragma unroll
        for (int h = 0; h < EMB; ++h)
            s = fmaf(__ldg(w_value + tid * EMB + h), __ldg(w_out + h), s);
        g_wvo[tid] = s;
        if (tid == 0) {
            float c = 0.f;
            for (int h = 0; h < EMB; ++h) c = fmaf(__ldg(b_value + h), __ldg(w_out + h), c);
            g_c  = c + __ldg(b_out);
            g_b0 = __ldg(b_out);
        }
    }

    if (i < Btot) {
        const int cur = __ldg(ids + i);
        if (i == 0) {
            for (int j = 0; j <= cur; ++j) g_starts[j] = 0;
        } else {
            const int prev = __ldg(ids + i - 1);
            for (int j = prev + 1; j <= cur; ++j) g_starts[j] = i;
        }
        if (i == Btot - 1) {
            for (int j = cur + 1; j <= Nimg; ++j) g_starts[j] = Btot;
        }
    }
}

// Kernel 2: ONE WARP = ONE CTA = ONE SEGMENT. grid=4096 single-warp CTAs
// distribute 27-28 per SM (vs 3-vs-4 CTA skew at 8 warps/CTA). No smem, no
// barriers. 8-way unrolled evict-first float4 loads, 16 lanes/row; only the
// score partial is shfl-reduced per row; value partials reduced once.
__global__ __launch_bounds__(32)
void pool_kernel(const float* __restrict__ emb,
                 const float* __restrict__ w_attn,
                 float* __restrict__ out,
                 int Btot, int Nimg) {
    const int n    = blockIdx.x;            // segment id
    const int lane = threadIdx.x;
    const int grp  = lane & 15;             // column slice [4*grp, 4*grp+4)
    const int half = lane >> 4;             // row slot 0/1

    const float4 wa = reinterpret_cast<const float4*>(w_attn)[grp];
    const float4 wv = reinterpret_cast<const float4*>(g_wvo)[grp];

    const int start = g_starts[n];
    const int end   = g_starts[n + 1];
    const int cnt   = end - start;

    float se0 = 0.f, sev0 = 0.f, se1 = 0.f, sev1 = 0.f;
    float se2 = 0.f, sev2 = 0.f, se3 = 0.f, sev3 = 0.f;

    const int mid = start + (cnt & ~15);    // 16 rows per iteration

    // ---- main loop: 8 independent LDG.128 (evict-first) front-batched ----
    for (int base = start; base < mid; base += 16) {
        float4 e[8];
#pragma unroll
        for (int u = 0; u < 8; ++u)
            e[u] = __ldcs(reinterpret_cast<const float4*>(
                       emb + (size_t)(base + u * 2 + half) * EMB) + grp);
#pragma unroll
        for (int u = 0; u < 8; ++u) {
            float sp = e[u].x * wa.x + e[u].y * wa.y + e[u].z * wa.z + e[u].w * wa.w;
            float vp = e[u].x * wv.x + e[u].y * wv.y + e[u].z * wv.z + e[u].w * wv.w;
#pragma unroll
            for (int o = 8; o; o >>= 1) sp += __shfl_xor_sync(0xffffffffu, sp, o);
            const float ex = __expf(sp);            // replicated on the 16-lane group
            if      ((u & 3) == 0) { se0 += ex; sev0 = fmaf(ex, vp, sev0); }
            else if ((u & 3) == 1) { se1 += ex; sev1 = fmaf(ex, vp, sev1); }
            else if ((u & 3) == 2) { se2 += ex; sev2 = fmaf(ex, vp, sev2); }
            else                   { se3 += ex; sev3 = fmaf(ex, vp, sev3); }
        }
    }

    // ---- masked tail (up to 15 rows) ----
    if (mid < end) {
#pragma unroll
        for (int u = 0; u < 8; ++u) {
            const int row = mid + u * 2 + half;
            const bool v = row < end;
            float4 e = make_float4(0.f, 0.f, 0.f, 0.f);
            if (v) e = __ldcs(reinterpret_cast<const float4*>(emb + (size_t)row * EMB) + grp);
            float sp = e.x * wa.x + e.y * wa.y + e.z * wa.z + e.w * wa.w;
            float vp = e.x * wv.x + e.y * wv.y + e.z * wv.z + e.w * wv.w;
#pragma unroll
            for (int o = 8; o; o >>= 1) sp += __shfl_xor_sync(0xffffffffu, sp, o);
            const float ex = v ? __expf(sp) : 0.f;
            se0 += ex; sev0 = fmaf(ex, vp, sev0);
        }
    }

    // ---- once-per-segment reduction (intra-warp only) ----
    float se  = (se0 + se1) + (se2 + se3);
    float sev = (sev0 + sev1) + (sev2 + sev3);
    se += __shfl_xor_sync(0xffffffffu, se, 16);     // se replicated in 16-groups
#pragma unroll
    for (int o = 16; o; o >>= 1) sev += __shfl_xor_sync(0xffffffffu, sev, o);

    const float r = (cnt == 0) ? g_b0 : (sev / se + g_c);   // replicated on all lanes

    if (lane == 0) {
        out[Btot + n]        = r;          // r_images
        out[Btot + Nimg + n] = (float)n;   // unique_ids
    }
    for (int i = start + lane; i < end; i += 32) out[i] = r;   // r_reflections
}

extern "C" void kernel_launch(void* const* d_in, const int* in_sizes, int n_in,
                              void* d_out, int out_size) {
    const float* emb     = (const float*)d_in[0];
    const int*   ids     = (const int*)  d_in[1];
    const float* w_attn  = (const float*)d_in[2];
    // d_in[3] = b_attn: cancels under softmax shift invariance
    const float* w_value = (const float*)d_in[4];
    const float* b_value = (const float*)d_in[5];
    const float* w_out   = (const float*)d_in[6];
    const float* b_out   = (const float*)d_in[7];
    float* out = (float*)d_out;

    const int Btot = in_sizes[0] / EMB;          // 1048576
    const int Nimg = (out_size - Btot) / 2;      // 4096

    bounds_kernel<<<(Btot + THREADS - 1) / THREADS, THREADS>>>(
        ids, w_value, b_value, w_out, b_out, Btot, Nimg);
    pool_kernel<<<Nimg, 32>>>(emb, w_attn, out, Btot, Nimg);
}